// round 14
// baseline (speedup 1.0000x reference)
#include <cuda_runtime.h>
#include <math.h>

#define NT 24
#define NPRED 12

// ---- scratch (static device globals; zero-initialized; no allocation) ----
__device__ float d_h1[2048 * 64], d_el1[2048], d_er1[2048];
__device__ float d_h2[2048 * 64], d_el2[2048], d_er2[2048];
__device__ float d_lh[2048 * 64];
__device__ unsigned long long d_WhhP[32 * 256];
__device__ unsigned long long d_WcombP[4 * 256];
__device__ float d_bcomb[256];
__device__ unsigned d_mask[512 * 16];   // zero-init; OR is idempotent across replays
__device__ int c_g0b[4];                // per-batch gat0 completion counters
__device__ int c_g1;                    // gat1 finisher counter (reset trigger)
__device__ int d_lflag[256];            // per-LSTM-block done flags

__device__ __forceinline__ float sigf(float x) {
    return __fdividef(1.0f, 1.0f + __expf(-x));
}
__device__ __forceinline__ float tanh_f(float x) {
    return 2.0f * sigf(2.0f * x) - 1.0f;
}
__device__ __forceinline__ unsigned long long pack2(float a, float b) {
    unsigned long long r;
    asm("mov.b64 %0, {%1,%2};" : "=l"(r) : "f"(a), "f"(b));
    return r;
}
__device__ __forceinline__ void unpack2(unsigned long long v, float& a, float& b) {
    asm("mov.b64 {%0,%1}, %2;" : "=f"(a), "=f"(b) : "l"(v));
}
__device__ __forceinline__ void fma2(unsigned long long& d, unsigned long long a,
                                     unsigned long long b) {
    asm("fma.rn.f32x2 %0, %1, %2, %0;" : "+l"(d) : "l"(a), "l"(b));
}
__device__ __forceinline__ void cpa16(float* smem_dst, const float4* gsrc) {
    unsigned u = (unsigned)__cvta_generic_to_shared(smem_dst);
    asm volatile("cp.async.cg.shared.global [%0], [%1], 16;" :: "r"(u), "l"(gsrc));
}
#define CPA_COMMIT() asm volatile("cp.async.commit_group;")
#define CPA_WAIT2() asm volatile("cp.async.wait_group 2;")

// ============ k_pre: 0-127 gatA | 128-135 wcomb | 136+ mask set ============
__global__ void __launch_bounds__(256) k_pre(
    const float* __restrict__ x, const float* __restrict__ Wfc,
    const float* __restrict__ bfc, const float* __restrict__ W1,
    const float* __restrict__ al, const float* __restrict__ ar,
    const float* __restrict__ Wih, const float* __restrict__ bih,
    const float* __restrict__ bhh, const float* __restrict__ Whh,
    const int* __restrict__ ei, int E) {
    int bid = blockIdx.x;
    int tid = threadIdx.x;

    if (bid >= 136) {
        int e = (bid - 136) * 256 + tid;
        if (e < E) {
            int s = ei[e], t = ei[E + e];
            atomicOr(&d_mask[s * 16 + (t >> 5)], 1u << (t & 31));
        }
        return;
    }
    if (bid >= 128) {
        int jb = (bid - 128) * 32;
        __shared__ float wih_s[32 * 64];
        __shared__ float whh_s[32 * 64];
        __shared__ float wc_s[32 * 8];
        {
            const float4* s1 = (const float4*)(Wih + jb * 64);
            const float4* s2 = (const float4*)(Whh + jb * 64);
            float4* t1 = (float4*)wih_s;
            float4* t2 = (float4*)whh_s;
            for (int q = tid; q < 512; q += 256) { t1[q] = s1[q]; t2[q] = s2[q]; }
        }
        __syncthreads();
        {
            int jl = tid >> 3, f = tid & 7;
            float s = 0.0f;
#pragma unroll
            for (int h = 0; h < 64; h++) s += Wfc[f * 64 + h] * wih_s[jl * 64 + h];
            wc_s[jl * 8 + f] = s;
            if (f == 0) {
                int j = jb + jl;
                float bj = bih[j] + bhh[j];
#pragma unroll
                for (int h = 0; h < 64; h++) bj += bfc[h] * wih_s[jl * 64 + h];
                d_bcomb[j] = bj;
            }
        }
        __syncthreads();
        {
            if (tid < 128) {
                int jl = tid & 31, fp = tid >> 5;
                d_WcombP[fp * 256 + jb + jl] =
                    pack2(wc_s[jl * 8 + 2 * fp], wc_s[jl * 8 + 2 * fp + 1]);
            }
#pragma unroll
            for (int q = 0; q < 4; q++) {
                int idx = tid + q * 256;
                int jl = idx & 31, k2 = idx >> 5;
                d_WhhP[k2 * 256 + jb + jl] =
                    pack2(whh_s[jl * 64 + 2 * k2], whh_s[jl * 64 + 2 * k2 + 1]);
            }
        }
        return;
    }

    // --- gatA: 16 nodes/block ---
    __shared__ float Ws[4096];
    __shared__ float wfs[512];
    __shared__ float bfs[64];
    __shared__ float in_s[16 * 64];
    __shared__ float xs[16 * 8];
    __shared__ float red[8][4][2];
    int bn0 = bid * 16;
    {
        const float4* src = (const float4*)W1;
        float4* dst = (float4*)Ws;
        for (int q = tid; q < 1024; q += 256) dst[q] = src[q];
        const float4* s2 = (const float4*)Wfc;
        float4* d2 = (float4*)wfs;
        if (tid < 128) d2[tid] = s2[tid];
    }
    if (tid < 64) bfs[tid] = bfc[tid];
    if (tid < 128) xs[tid] = x[(bn0 + (tid >> 3)) * (NT * 8) + (NT - 1) * 8 + (tid & 7)];
    __syncthreads();
    for (int idx = tid; idx < 1024; idx += 256) {
        int nd = idx >> 6, ii = idx & 63;
        float v = bfs[ii];
#pragma unroll
        for (int f = 0; f < 8; f++) v += xs[nd * 8 + f] * wfs[f * 64 + ii];
        in_s[idx] = v;
    }
    __syncthreads();
    int i = tid & 63, grp = tid >> 6;
    float wcol[64];
#pragma unroll
    for (int k = 0; k < 64; k++) wcol[k] = Ws[k * 64 + i];
    float a_l = al[i], a_r = ar[i];
    float pl[4], pr[4];
#pragma unroll
    for (int q = 0; q < 4; q++) {
        int nd = grp * 4 + q;
        float h = 0.0f;
#pragma unroll
        for (int k = 0; k < 64; k++) h += in_s[nd * 64 + k] * wcol[k];
        d_h1[(size_t)(bn0 + nd) * 64 + i] = h;
        pl[q] = h * a_l; pr[q] = h * a_r;
    }
#pragma unroll
    for (int q = 0; q < 4; q++) {
#pragma unroll
        for (int o = 16; o; o >>= 1) {
            pl[q] += __shfl_xor_sync(~0u, pl[q], o);
            pr[q] += __shfl_xor_sync(~0u, pr[q], o);
        }
    }
    int wp = tid >> 5, lane = tid & 31;
    if (lane == 0) {
#pragma unroll
        for (int q = 0; q < 4; q++) { red[wp][q][0] = pl[q]; red[wp][q][1] = pr[q]; }
    }
    __syncthreads();
    if (tid < 32) {
        int nd = tid >> 1, v = tid & 1;
        int g = nd >> 2, q = nd & 3;
        float s = red[2 * g][q][v] + red[2 * g + 1][q][v];
        if (v) d_er1[bn0 + nd] = s;
        else d_el1[bn0 + nd] = s;
    }
}

// ---- GAT core: 8 targets/block (proven) ----
__device__ __forceinline__ void gat_core(
    int base, int m0, const float* __restrict__ hsrc, const float* __restrict__ elv,
    const float* __restrict__ erv, const float* __restrict__ bias,
    float* p_s, float* hbuf, float* gs, unsigned* mask_s,
    float* el_s, float* inv_s, float* sred) {
    int tid = threadIdx.x;
    const float4* hb4 = (const float4*)(hsrc + (size_t)base * 64);

#pragma unroll
    for (int k = 0; k < 3; k++) {
        cpa16(&hbuf[k * 2048 + tid * 4], &hb4[k * 512 + tid]);
        cpa16(&hbuf[k * 2048 + (256 + tid) * 4], &hb4[k * 512 + 256 + tid]);
        CPA_COMMIT();
    }
    for (int q = tid; q < 512; q += 256) gs[q] = erv[base + q];
    if (tid < 8) el_s[tid] = elv[base + m0 + tid];
    if (tid < 128) mask_s[tid] = d_mask[(m0 + (tid >> 4)) * 16 + (tid & 15)];
    __syncthreads();

    int m = tid & 7, ngrp = tid >> 3;
    {
        float elm = el_s[m];
        unsigned mw = mask_s[m * 16 + (ngrp >> 1)];
        int shb = (ngrp & 1) * 16;
        int nb = ngrp * 16;
        float s = 0.0f;
#pragma unroll
        for (int k = 0; k < 16; k++) {
            int n = nb + k;
            float e = elm + gs[n];
            e = (e >= 0.0f) ? e : 0.2f * e;
            float pe = ((mw >> (shb + k)) & 1u) ? __expf(e) : 0.0f;
            p_s[n * 8 + m] = pe;
            s += pe;
        }
        s += __shfl_xor_sync(~0u, s, 8);
        s += __shfl_xor_sync(~0u, s, 16);
        int lane = tid & 31, w = tid >> 5;
        if (lane < 8) sred[w * 8 + lane] = s;
    }
    __syncthreads();
    if (tid < 8) {
        float s = 0.0f;
#pragma unroll
        for (int q = 0; q < 8; q++) s += sred[q * 8 + tid];
        inv_s[tid] = __fdividef(1.0f, s);
    }

    int i = tid & 63, sub = tid >> 6;
    unsigned long long acc[4];
#pragma unroll
    for (int q = 0; q < 4; q++) acc[q] = 0ull;

#pragma unroll 1
    for (int c = 0; c < 16; c++) {
        CPA_WAIT2();
        __syncthreads();
        const float* hc = hbuf + (c % 3) * 2048;
        const float* pc = p_s + c * 32 * 8;
#pragma unroll
        for (int nn = 0; nn < 8; nn++) {
            int nl = sub * 8 + nn;
            float h = hc[nl * 64 + i];
            unsigned long long hd = pack2(h, h);
            const ulonglong2* pp = (const ulonglong2*)&pc[nl * 8];
            ulonglong2 pa = pp[0], pb = pp[1];
            fma2(acc[0], pa.x, hd);
            fma2(acc[1], pa.y, hd);
            fma2(acc[2], pb.x, hd);
            fma2(acc[3], pb.y, hd);
        }
        __syncthreads();
        if (c + 3 < 16) {
            cpa16(&hbuf[(c % 3) * 2048 + tid * 4], &hb4[(c + 3) * 512 + tid]);
            cpa16(&hbuf[(c % 3) * 2048 + (256 + tid) * 4], &hb4[(c + 3) * 512 + 256 + tid]);
        }
        CPA_COMMIT();
    }

    float* parts = hbuf;
#pragma unroll
    for (int q = 0; q < 4; q++) {
        float a, bv;
        unpack2(acc[q], a, bv);
        parts[sub * 512 + (2 * q) * 64 + i] = a;
        parts[sub * 512 + (2 * q + 1) * 64 + i] = bv;
    }
    __syncthreads();
#pragma unroll
    for (int q = 0; q < 2; q++) {
        int oo = tid + q * 256;
        float v = parts[oo] + parts[512 + oo] + parts[1024 + oo] + parts[1536 + oo];
        v = v * inv_s[oo >> 6] + bias[oo & 63];
        gs[oo] = 0.5f * v * (1.0f + erff(v * 0.70710678118654752f));
    }
    __syncthreads();
}

// ============ k_all: 768 blocks ============
// bids 0-255 LSTM | 256-511 gatB0 | 512-767 gatB1 (device-side deps)
__global__ void __launch_bounds__(256, 2) k_all(
    const float* __restrict__ x, const float* __restrict__ bias1,
    const float* __restrict__ W2, const float* __restrict__ al2,
    const float* __restrict__ ar2, const float* __restrict__ bias2,
    const float* __restrict__ gl, const float* __restrict__ bl,
    const float* __restrict__ gg, const float* __restrict__ bg,
    const float* __restrict__ Wd, const float* __restrict__ bd,
    float* __restrict__ out) {
    __shared__ __align__(16) float buf[10752];
    __shared__ unsigned mask_s[128];
    __shared__ float el_s[8], inv_s[8], sred[64];
    __shared__ float redE[8][4];
    int tid = threadIdx.x;
    int bid = blockIdx.x;

    if (bid < 256) {
        // ---- LSTM: 8 rows/block, 2 x 4-row accumulation groups ----
        int row0 = bid * 8;
        float* xs_all = buf;
        float* h_s = buf + 1536;
        float* gates = buf + 2048;
        {
            const float4* src = (const float4*)(x + (size_t)row0 * 192);
            float4* dst = (float4*)xs_all;
            for (int q = tid; q < 384; q += 256) dst[q] = src[q];
        }
        for (int q = tid; q < 512; q += 256) h_s[q] = 0.0f;
        unsigned long long wd[32];
#pragma unroll
        for (int kk = 0; kk < 32; kk++) wd[kk] = d_WhhP[kk * 256 + tid];
        unsigned long long wcd[4];
#pragma unroll
        for (int fp = 0; fp < 4; fp++) wcd[fp] = d_WcombP[fp * 256 + tid];
        float bj = d_bcomb[tid];
        float c0 = 0.0f, c1 = 0.0f;
        __syncthreads();

        const ulonglong2* h2p = (const ulonglong2*)h_s;

        for (int t = 0; t < NT; t++) {
#pragma unroll
            for (int grp = 0; grp < 2; grp++) {
                unsigned long long acc[4];
#pragma unroll
                for (int r4 = 0; r4 < 4; r4++) {
                    int r = grp * 4 + r4;
                    unsigned long long a = pack2(bj, 0.0f);
                    const unsigned long long* xp =
                        (const unsigned long long*)&xs_all[r * 192 + t * 8];
#pragma unroll
                    for (int fp = 0; fp < 4; fp++) fma2(a, xp[fp], wcd[fp]);
                    acc[r4] = a;
                }
#pragma unroll
                for (int k4 = 0; k4 < 16; k4++) {
#pragma unroll
                    for (int r4 = 0; r4 < 4; r4++) {
                        ulonglong2 hv = h2p[(grp * 4 + r4) * 16 + k4];
                        fma2(acc[r4], hv.x, wd[2 * k4]);
                        fma2(acc[r4], hv.y, wd[2 * k4 + 1]);
                    }
                }
#pragma unroll
                for (int r4 = 0; r4 < 4; r4++) {
                    float a, bv;
                    unpack2(acc[r4], a, bv);
                    gates[(grp * 4 + r4) * 256 + tid] = a + bv;
                }
            }
            __syncthreads();
            {
                int r = tid >> 6, ii = tid & 63;
                float gi = gates[r * 256 + ii];
                float gf = gates[r * 256 + 64 + ii];
                float gG = gates[r * 256 + 128 + ii];
                float go = gates[r * 256 + 192 + ii];
                float c = sigf(gf) * c0 + sigf(gi) * tanh_f(gG);
                c0 = c;
                h_s[r * 64 + ii] = sigf(go) * tanh_f(c);
            }
            {
                int idx = tid + 256;
                int r = idx >> 6, ii = idx & 63;
                float gi = gates[r * 256 + ii];
                float gf = gates[r * 256 + 64 + ii];
                float gG = gates[r * 256 + 128 + ii];
                float go = gates[r * 256 + 192 + ii];
                float c = sigf(gf) * c1 + sigf(gi) * tanh_f(gG);
                c1 = c;
                h_s[r * 64 + ii] = sigf(go) * tanh_f(c);
            }
            __syncthreads();
        }
        for (int q = tid; q < 512; q += 256) d_lh[(size_t)row0 * 64 + q] = h_s[q];
        __threadfence();
        __syncthreads();
        if (tid == 0) atomicExch(&d_lflag[bid], 1);
        return;
    }

    if (bid < 512) {
        // ---- gatB layer 0 + fused layer-2 projection ----
        int widx = bid - 256;
        int b = widx >> 6, m0 = (widx & 63) * 8;
        int base = b * 512;
        float* p_s = buf;
        float* hbuf = buf + 4096;
        float* gs = buf + 10240;

        gat_core(base, m0, d_h1, d_el1, d_er1, bias1, p_s, hbuf, gs, mask_s, el_s, inv_s, sred);

        for (int q = tid; q < 4096; q += 256) p_s[q] = W2[q];
        __syncthreads();
        int i = tid & 63, g = tid >> 6;
        float h2a = 0.0f, h2b = 0.0f;
#pragma unroll
        for (int k = 0; k < 64; k++) {
            float wv = p_s[k * 64 + i];
            h2a += gs[g * 64 + k] * wv;
            h2b += gs[(g + 4) * 64 + k] * wv;
        }
        d_h2[(size_t)(base + m0 + g) * 64 + i] = h2a;
        d_h2[(size_t)(base + m0 + g + 4) * 64 + i] = h2b;
        float a_l = al2[i], a_r = ar2[i];
        float pla = h2a * a_l, pra = h2a * a_r, plb = h2b * a_l, prb = h2b * a_r;
#pragma unroll
        for (int o = 16; o; o >>= 1) {
            pla += __shfl_xor_sync(~0u, pla, o);
            pra += __shfl_xor_sync(~0u, pra, o);
            plb += __shfl_xor_sync(~0u, plb, o);
            prb += __shfl_xor_sync(~0u, prb, o);
        }
        int lane = tid & 31, w = tid >> 5;
        if (lane == 0) { redE[w][0] = pla; redE[w][1] = pra; redE[w][2] = plb; redE[w][3] = prb; }
        __syncthreads();
        if (tid < 16) {
            int mm = tid >> 1, v = tid & 1;
            int g2 = mm & 3, hi = mm >> 2;
            float s = redE[2 * g2][hi * 2 + v] + redE[2 * g2 + 1][hi * 2 + v];
            if (v) d_er2[base + m0 + mm] = s;
            else d_el2[base + m0 + mm] = s;
        }
        __threadfence();
        __syncthreads();
        if (tid == 0) atomicAdd(&c_g0b[b], 1);
        return;
    }

    // ---- gatB layer 1 + fused LN + decode ----
    {
        int widx = bid - 512;
        int b = widx >> 6, m0 = (widx & 63) * 8;
        int base = b * 512;
        float* p_s = buf;
        float* hbuf = buf + 4096;
        float* gs = buf + 10240;

        // wait for this batch's 64 gat0 blocks
        if (tid == 0) {
            while (atomicAdd(&c_g0b[b], 0) < 64) __nanosleep(128);
        }
        __syncthreads();
        __threadfence();

        gat_core(base, m0, d_h2, d_el2, d_er2, bias2, p_s, hbuf, gs, mask_s, el_s, inv_s, sred);

        // wait for the one LSTM block producing rows [base+m0, base+m0+8)
        if (tid == 0) {
            int lb = (base + m0) >> 3;
            while (atomicAdd(&d_lflag[lb], 0) == 0) __nanosleep(128);
        }
        __syncthreads();
        __threadfence();

        float* lh_s = hbuf;
        float* Wds = hbuf + 512;
        for (int q = tid; q < 512; q += 256) lh_s[q] = d_lh[(size_t)(base + m0) * 64 + q];
        for (int q = tid; q < 768; q += 256) Wds[q] = Wd[q];
        __syncthreads();
        int lane = tid & 31, w = tid >> 5;
        int ia = lane, ib = lane + 32;
        float vg0 = gs[w * 64 + ia], vg1 = gs[w * 64 + ib];
        float vl0 = lh_s[w * 64 + ia], vl1 = lh_s[w * 64 + ib];
        float s1 = vg0 + vg1, s2 = vg0 * vg0 + vg1 * vg1;
        float s3 = vl0 + vl1, s4 = vl0 * vl0 + vl1 * vl1;
#pragma unroll
        for (int o = 16; o; o >>= 1) {
            s1 += __shfl_xor_sync(~0u, s1, o);
            s2 += __shfl_xor_sync(~0u, s2, o);
            s3 += __shfl_xor_sync(~0u, s3, o);
            s4 += __shfl_xor_sync(~0u, s4, o);
        }
        const float invH = 1.0f / 64.0f;
        float mug = s1 * invH, varg = s2 * invH - mug * mug;
        float mul_ = s3 * invH, varl = s4 * invH - mul_ * mul_;
        float rg = rsqrtf(varg + 1e-5f), rl = rsqrtf(varl + 1e-5f);
        float h0 = (vg0 - mug) * rg * gg[ia] + bg[ia] + (vl0 - mul_) * rl * gl[ia] + bl[ia];
        float h1v = (vg1 - mug) * rg * gg[ib] + bg[ib] + (vl1 - mul_) * rl * gl[ib] + bl[ib];
        __syncwarp();
        lh_s[w * 64 + ia] = h0;
        lh_s[w * 64 + ib] = h1v;
        __syncwarp();
        if (lane < NPRED) {
            float o = bd[lane];
#pragma unroll
            for (int k = 0; k < 64; k++) o += lh_s[w * 64 + k] * Wds[k * NPRED + lane];
            out[(size_t)(base + m0 + w) * NPRED + lane] = o;
        }
        // last gat1 finisher resets counters + flags for graph replay
        __syncthreads();
        if (tid == 0) {
            int old = atomicAdd(&c_g1, 1);
            if (old == 255) {
                for (int q = 0; q < 256; q++) d_lflag[q] = 0;
                atomicExch(&c_g0b[0], 0); atomicExch(&c_g0b[1], 0);
                atomicExch(&c_g0b[2], 0); atomicExch(&c_g0b[3], 0);
                atomicExch(&c_g1, 0);
            }
        }
    }
}

extern "C" void kernel_launch(void* const* d_in, const int* in_sizes, int n_in,
                              void* d_out, int out_size) {
    const float* x    = (const float*)d_in[0];
    const int*   ei   = (const int*)d_in[1];
    const float* Wfc  = (const float*)d_in[2];
    const float* bfc  = (const float*)d_in[3];
    const float* W1   = (const float*)d_in[4];
    const float* al1  = (const float*)d_in[5];
    const float* ar1  = (const float*)d_in[6];
    const float* bias1= (const float*)d_in[7];
    const float* W2   = (const float*)d_in[8];
    const float* al2  = (const float*)d_in[9];
    const float* ar2  = (const float*)d_in[10];
    const float* bias2= (const float*)d_in[11];
    const float* Wih  = (const float*)d_in[12];
    const float* Whh  = (const float*)d_in[13];
    const float* bih  = (const float*)d_in[14];
    const float* bhh  = (const float*)d_in[15];
    const float* gl   = (const float*)d_in[16];
    const float* bl   = (const float*)d_in[17];
    const float* gg   = (const float*)d_in[18];
    const float* bg   = (const float*)d_in[19];
    const float* Wd   = (const float*)d_in[20];
    const float* bd   = (const float*)d_in[21];
    float* out = (float*)d_out;

    int E = in_sizes[1] / 2;
    int maskBlocks = (E + 255) / 256;

    k_pre<<<136 + maskBlocks, 256>>>(x, Wfc, bfc, W1, al1, ar1, Wih, bih, bhh, Whh, ei, E);
    k_all<<<768, 256>>>(x, bias1, W2, al2, ar2, bias2, gl, bl, gg, bg, Wd, bd, out);
}

// round 15
// speedup vs baseline: 1.1479x; 1.1479x over previous
#include <cuda_runtime.h>
#include <math.h>

#define NT 24
#define NPRED 12
#define MAXN 96   // max neighbors per target row (mean ~17, binomial tail safe)

// ---- scratch (static device globals; zero-initialized; no allocation) ----
__device__ float d_h1[2048 * 64], d_el1[2048], d_er1[2048];
__device__ float d_h2[2048 * 64], d_el2[2048], d_er2[2048];
__device__ float d_lh[2048 * 64];
__device__ unsigned long long d_WhhP[32 * 256];
__device__ unsigned long long d_WcombP[4 * 256];
__device__ float d_bcomb[256];
__device__ unsigned d_mask[512 * 16];   // zero-init; OR is idempotent across replays

__device__ __forceinline__ float sigf(float x) {
    return __fdividef(1.0f, 1.0f + __expf(-x));
}
__device__ __forceinline__ float tanh_f(float x) {
    return 2.0f * sigf(2.0f * x) - 1.0f;
}
__device__ __forceinline__ unsigned long long pack2(float a, float b) {
    unsigned long long r;
    asm("mov.b64 %0, {%1,%2};" : "=l"(r) : "f"(a), "f"(b));
    return r;
}
__device__ __forceinline__ void unpack2(unsigned long long v, float& a, float& b) {
    asm("mov.b64 {%0,%1}, %2;" : "=f"(a), "=f"(b) : "l"(v));
}
__device__ __forceinline__ void fma2(unsigned long long& d, unsigned long long a,
                                     unsigned long long b) {
    asm("fma.rn.f32x2 %0, %1, %2, %0;" : "+l"(d) : "l"(a), "l"(b));
}

// ============ k_pre: 0-127 gatA | 128-135 wcomb | 136+ mask set ============
__global__ void __launch_bounds__(256) k_pre(
    const float* __restrict__ x, const float* __restrict__ Wfc,
    const float* __restrict__ bfc, const float* __restrict__ W1,
    const float* __restrict__ al, const float* __restrict__ ar,
    const float* __restrict__ Wih, const float* __restrict__ bih,
    const float* __restrict__ bhh, const float* __restrict__ Whh,
    const int* __restrict__ ei, int E) {
    int bid = blockIdx.x;
    int tid = threadIdx.x;

    if (bid >= 136) {
        int e = (bid - 136) * 256 + tid;
        if (e < E) {
            int s = ei[e], t = ei[E + e];
            atomicOr(&d_mask[s * 16 + (t >> 5)], 1u << (t & 31));
        }
        return;
    }
    if (bid >= 128) {
        int jb = (bid - 128) * 32;
        __shared__ float wih_s[32 * 64];
        __shared__ float whh_s[32 * 64];
        __shared__ float wc_s[32 * 8];
        {
            const float4* s1 = (const float4*)(Wih + jb * 64);
            const float4* s2 = (const float4*)(Whh + jb * 64);
            float4* t1 = (float4*)wih_s;
            float4* t2 = (float4*)whh_s;
            for (int q = tid; q < 512; q += 256) { t1[q] = s1[q]; t2[q] = s2[q]; }
        }
        __syncthreads();
        {
            int jl = tid >> 3, f = tid & 7;
            float s = 0.0f;
#pragma unroll
            for (int h = 0; h < 64; h++) s += Wfc[f * 64 + h] * wih_s[jl * 64 + h];
            wc_s[jl * 8 + f] = s;
            if (f == 0) {
                int j = jb + jl;
                float bj = bih[j] + bhh[j];
#pragma unroll
                for (int h = 0; h < 64; h++) bj += bfc[h] * wih_s[jl * 64 + h];
                d_bcomb[j] = bj;
            }
        }
        __syncthreads();
        {
            if (tid < 128) {
                int jl = tid & 31, fp = tid >> 5;
                d_WcombP[fp * 256 + jb + jl] =
                    pack2(wc_s[jl * 8 + 2 * fp], wc_s[jl * 8 + 2 * fp + 1]);
            }
#pragma unroll
            for (int q = 0; q < 4; q++) {
                int idx = tid + q * 256;
                int jl = idx & 31, k2 = idx >> 5;
                d_WhhP[k2 * 256 + jb + jl] =
                    pack2(whh_s[jl * 64 + 2 * k2], whh_s[jl * 64 + 2 * k2 + 1]);
            }
        }
        return;
    }

    // --- gatA: 16 nodes/block ---
    __shared__ float Ws[4096];
    __shared__ float wfs[512];
    __shared__ float bfs[64];
    __shared__ float in_s[16 * 64];
    __shared__ float xs[16 * 8];
    __shared__ float red[8][4][2];
    int bn0 = bid * 16;
    {
        const float4* src = (const float4*)W1;
        float4* dst = (float4*)Ws;
        for (int q = tid; q < 1024; q += 256) dst[q] = src[q];
        const float4* s2 = (const float4*)Wfc;
        float4* d2 = (float4*)wfs;
        if (tid < 128) d2[tid] = s2[tid];
    }
    if (tid < 64) bfs[tid] = bfc[tid];
    if (tid < 128) xs[tid] = x[(bn0 + (tid >> 3)) * (NT * 8) + (NT - 1) * 8 + (tid & 7)];
    __syncthreads();
    for (int idx = tid; idx < 1024; idx += 256) {
        int nd = idx >> 6, ii = idx & 63;
        float v = bfs[ii];
#pragma unroll
        for (int f = 0; f < 8; f++) v += xs[nd * 8 + f] * wfs[f * 64 + ii];
        in_s[idx] = v;
    }
    __syncthreads();
    int i = tid & 63, grp = tid >> 6;
    float wcol[64];
#pragma unroll
    for (int k = 0; k < 64; k++) wcol[k] = Ws[k * 64 + i];
    float a_l = al[i], a_r = ar[i];
    float pl[4], pr[4];
#pragma unroll
    for (int q = 0; q < 4; q++) {
        int nd = grp * 4 + q;
        float h = 0.0f;
#pragma unroll
        for (int k = 0; k < 64; k++) h += in_s[nd * 64 + k] * wcol[k];
        d_h1[(size_t)(bn0 + nd) * 64 + i] = h;
        pl[q] = h * a_l; pr[q] = h * a_r;
    }
#pragma unroll
    for (int q = 0; q < 4; q++) {
#pragma unroll
        for (int o = 16; o; o >>= 1) {
            pl[q] += __shfl_xor_sync(~0u, pl[q], o);
            pr[q] += __shfl_xor_sync(~0u, pr[q], o);
        }
    }
    int wp = tid >> 5, lane = tid & 31;
    if (lane == 0) {
#pragma unroll
        for (int q = 0; q < 4; q++) { red[wp][q][0] = pl[q]; red[wp][q][1] = pr[q]; }
    }
    __syncthreads();
    if (tid < 32) {
        int nd = tid >> 1, v = tid & 1;
        int g = nd >> 2, q = nd & 3;
        float s = red[2 * g][q][v] + red[2 * g + 1][q][v];
        if (v) d_er1[bn0 + nd] = s;
        else d_el1[bn0 + nd] = s;
    }
}

// ---- sparse GAT core: 8 targets/block, warp w handles target m0+w ----
// Writes gelu'd output rows into gs[8*64].
__device__ __forceinline__ void gat_sparse(
    int base, int m0, const float* __restrict__ hsrc, const float* __restrict__ elv,
    const float* __restrict__ erv, const float* __restrict__ bias,
    float* er_s, float* gs, float* pnb_s, int* nbr_s, unsigned* mask_s,
    int* cnt_s, float* el_s, float* inv_s) {
    int tid = threadIdx.x;
    int lane = tid & 31, w = tid >> 5;

    for (int q = tid; q < 512; q += 256) er_s[q] = erv[base + q];
    if (tid < 8) el_s[tid] = elv[base + m0 + tid];
    if (tid < 128) mask_s[tid] = d_mask[(m0 + (tid >> 4)) * 16 + (tid & 15)];
    __syncthreads();

    // --- phase A: bit-extract neighbors + exp, warp prefix-scan slots ---
    {
        unsigned mw = (lane < 16) ? mask_s[w * 16 + lane] : 0u;
        int c = __popc(mw);
        int off = c;
#pragma unroll
        for (int o = 1; o < 32; o <<= 1) {
            int v = __shfl_up_sync(~0u, off, o);
            if (lane >= o) off += v;
        }
        off -= c;  // exclusive prefix
        float elm = el_s[w];
        float sum = 0.0f;
        int slot = off;
        while (mw) {
            int b = __ffs(mw) - 1;
            mw &= mw - 1;
            int n = lane * 32 + b;
            float e = elm + er_s[n];
            e = (e >= 0.0f) ? e : 0.2f * e;
            float pe = __expf(e);
            if (slot < MAXN) {
                nbr_s[w * MAXN + slot] = n;
                pnb_s[w * MAXN + slot] = pe;
            }
            slot++;
            sum += pe;
        }
#pragma unroll
        for (int o = 16; o; o >>= 1) sum += __shfl_xor_sync(~0u, sum, o);
        if (lane == 0) inv_s[w] = __fdividef(1.0f, sum);
        if (lane == 31) cnt_s[w] = (off < MAXN) ? off : MAXN;  // total (c=0 at lane 31)
    }
    __syncthreads();

    // --- phase B: sparse aggregate, lane covers features i2 = 2*lane, +1 ---
    {
        int K = cnt_s[w];
        float inv = inv_s[w];
        const float* hb = hsrc + (size_t)base * 64;
        int i2 = lane * 2;
        float ax = 0.0f, ay = 0.0f;
        int s = 0;
        for (; s + 4 <= K; s += 4) {
            int n0 = nbr_s[w * MAXN + s], n1 = nbr_s[w * MAXN + s + 1];
            int n2 = nbr_s[w * MAXN + s + 2], n3 = nbr_s[w * MAXN + s + 3];
            float p0 = pnb_s[w * MAXN + s], p1 = pnb_s[w * MAXN + s + 1];
            float p2 = pnb_s[w * MAXN + s + 2], p3 = pnb_s[w * MAXN + s + 3];
            float2 v0 = *(const float2*)&hb[(size_t)n0 * 64 + i2];
            float2 v1 = *(const float2*)&hb[(size_t)n1 * 64 + i2];
            float2 v2 = *(const float2*)&hb[(size_t)n2 * 64 + i2];
            float2 v3 = *(const float2*)&hb[(size_t)n3 * 64 + i2];
            ax += p0 * v0.x + p1 * v1.x + p2 * v2.x + p3 * v3.x;
            ay += p0 * v0.y + p1 * v1.y + p2 * v2.y + p3 * v3.y;
        }
        for (; s < K; s++) {
            int n = nbr_s[w * MAXN + s];
            float p = pnb_s[w * MAXN + s];
            float2 v = *(const float2*)&hb[(size_t)n * 64 + i2];
            ax += p * v.x;
            ay += p * v.y;
        }
        float vx = ax * inv + bias[i2];
        float vy = ay * inv + bias[i2 + 1];
        gs[w * 64 + i2] = 0.5f * vx * (1.0f + erff(vx * 0.70710678118654752f));
        gs[w * 64 + i2 + 1] = 0.5f * vy * (1.0f + erff(vy * 0.70710678118654752f));
    }
    __syncthreads();
}

// ============ k_main: bids 0-255 LSTM | 256-511 gatB0 (sparse) ============
__global__ void __launch_bounds__(256, 2) k_main(
    const float* __restrict__ x, const float* __restrict__ bias1,
    const float* __restrict__ W2, const float* __restrict__ al2,
    const float* __restrict__ ar2) {
    __shared__ __align__(16) float fbuf[5888]; // LSTM: xs1536|h512|gates2048 ; gat: W2s4096|er512|gs512|pnb768
    __shared__ int nbr_s[8 * MAXN];
    __shared__ unsigned mask_s[128];
    __shared__ int cnt_s[8];
    __shared__ float el_s[8], inv_s[8];
    __shared__ float redE[8][4];
    int tid = threadIdx.x;
    int bid = blockIdx.x;

    if (bid < 256) {
        // ---- LSTM: 8 rows/block, 2 x 4-row accumulation groups ----
        int row0 = bid * 8;
        float* xs_all = fbuf;
        float* h_s = fbuf + 1536;
        float* gates = fbuf + 2048;
        {
            const float4* src = (const float4*)(x + (size_t)row0 * 192);
            float4* dst = (float4*)xs_all;
            for (int q = tid; q < 384; q += 256) dst[q] = src[q];
        }
        for (int q = tid; q < 512; q += 256) h_s[q] = 0.0f;
        unsigned long long wd[32];
#pragma unroll
        for (int kk = 0; kk < 32; kk++) wd[kk] = d_WhhP[kk * 256 + tid];
        unsigned long long wcd[4];
#pragma unroll
        for (int fp = 0; fp < 4; fp++) wcd[fp] = d_WcombP[fp * 256 + tid];
        float bj = d_bcomb[tid];
        float c0 = 0.0f, c1 = 0.0f;
        __syncthreads();

        const ulonglong2* h2p = (const ulonglong2*)h_s;

        for (int t = 0; t < NT; t++) {
#pragma unroll
            for (int grp = 0; grp < 2; grp++) {
                unsigned long long acc[4];
#pragma unroll
                for (int r4 = 0; r4 < 4; r4++) {
                    int r = grp * 4 + r4;
                    unsigned long long a = pack2(bj, 0.0f);
                    const unsigned long long* xp =
                        (const unsigned long long*)&xs_all[r * 192 + t * 8];
#pragma unroll
                    for (int fp = 0; fp < 4; fp++) fma2(a, xp[fp], wcd[fp]);
                    acc[r4] = a;
                }
#pragma unroll
                for (int k4 = 0; k4 < 16; k4++) {
#pragma unroll
                    for (int r4 = 0; r4 < 4; r4++) {
                        ulonglong2 hv = h2p[(grp * 4 + r4) * 16 + k4];
                        fma2(acc[r4], hv.x, wd[2 * k4]);
                        fma2(acc[r4], hv.y, wd[2 * k4 + 1]);
                    }
                }
#pragma unroll
                for (int r4 = 0; r4 < 4; r4++) {
                    float a, bv;
                    unpack2(acc[r4], a, bv);
                    gates[(grp * 4 + r4) * 256 + tid] = a + bv;
                }
            }
            __syncthreads();
            {
                int r = tid >> 6, ii = tid & 63;
                float gi = gates[r * 256 + ii];
                float gf = gates[r * 256 + 64 + ii];
                float gG = gates[r * 256 + 128 + ii];
                float go = gates[r * 256 + 192 + ii];
                float c = sigf(gf) * c0 + sigf(gi) * tanh_f(gG);
                c0 = c;
                h_s[r * 64 + ii] = sigf(go) * tanh_f(c);
            }
            {
                int idx = tid + 256;
                int r = idx >> 6, ii = idx & 63;
                float gi = gates[r * 256 + ii];
                float gf = gates[r * 256 + 64 + ii];
                float gG = gates[r * 256 + 128 + ii];
                float go = gates[r * 256 + 192 + ii];
                float c = sigf(gf) * c1 + sigf(gi) * tanh_f(gG);
                c1 = c;
                h_s[r * 64 + ii] = sigf(go) * tanh_f(c);
            }
            __syncthreads();
        }
        for (int q = tid; q < 512; q += 256) d_lh[(size_t)row0 * 64 + q] = h_s[q];
        return;
    }

    // ---- gatB layer 0 (sparse) + fused layer-2 projection ----
    int widx = bid - 256;
    int b = widx >> 6, m0 = (widx & 63) * 8;
    int base = b * 512;
    float* W2s = fbuf;
    float* er_s = fbuf + 4096;
    float* gs = fbuf + 4608;
    float* pnb_s = fbuf + 5120;

    // stage W2 early (overlaps sparse gat latency)
    for (int q = tid; q < 4096; q += 256) W2s[q] = W2[q];

    gat_sparse(base, m0, d_h1, d_el1, d_er1, bias1,
               er_s, gs, pnb_s, nbr_s, mask_s, cnt_s, el_s, inv_s);

    int i = tid & 63, g = tid >> 6;
    float h2a = 0.0f, h2b = 0.0f;
#pragma unroll
    for (int k = 0; k < 64; k++) {
        float wv = W2s[k * 64 + i];
        h2a += gs[g * 64 + k] * wv;
        h2b += gs[(g + 4) * 64 + k] * wv;
    }
    d_h2[(size_t)(base + m0 + g) * 64 + i] = h2a;
    d_h2[(size_t)(base + m0 + g + 4) * 64 + i] = h2b;
    float a_l = al2[i], a_r = ar2[i];
    float pla = h2a * a_l, pra = h2a * a_r, plb = h2b * a_l, prb = h2b * a_r;
#pragma unroll
    for (int o = 16; o; o >>= 1) {
        pla += __shfl_xor_sync(~0u, pla, o);
        pra += __shfl_xor_sync(~0u, pra, o);
        plb += __shfl_xor_sync(~0u, plb, o);
        prb += __shfl_xor_sync(~0u, prb, o);
    }
    int lane = tid & 31, w = tid >> 5;
    if (lane == 0) { redE[w][0] = pla; redE[w][1] = pra; redE[w][2] = plb; redE[w][3] = prb; }
    __syncthreads();
    if (tid < 16) {
        int mm = tid >> 1, v = tid & 1;
        int g2 = mm & 3, hi = mm >> 2;
        float s = redE[2 * g2][hi * 2 + v] + redE[2 * g2 + 1][hi * 2 + v];
        if (v) d_er2[base + m0 + mm] = s;
        else d_el2[base + m0 + mm] = s;
    }
}

// ============ k_gat1: 256 blocks x 8 targets (sparse) + LN + decode ============
__global__ void __launch_bounds__(256, 2) k_gat1(
    const float* __restrict__ bias2, const float* __restrict__ gl,
    const float* __restrict__ bl, const float* __restrict__ gg,
    const float* __restrict__ bg, const float* __restrict__ Wd,
    const float* __restrict__ bd, float* __restrict__ out) {
    __shared__ __align__(16) float fbuf[5888];
    __shared__ int nbr_s[8 * MAXN];
    __shared__ unsigned mask_s[128];
    __shared__ int cnt_s[8];
    __shared__ float el_s[8], inv_s[8];
    int tid = threadIdx.x;
    int b = blockIdx.x >> 6, m0 = (blockIdx.x & 63) * 8;
    int base = b * 512;
    float* lh_s = fbuf;          // 512
    float* Wds = fbuf + 512;     // 768
    float* er_s = fbuf + 4096;
    float* gs = fbuf + 4608;
    float* pnb_s = fbuf + 5120;

    // stage lh + Wd early (overlaps sparse gat latency)
    for (int q = tid; q < 512; q += 256) lh_s[q] = d_lh[(size_t)(base + m0) * 64 + q];
    for (int q = tid; q < 768; q += 256) Wds[q] = Wd[q];

    gat_sparse(base, m0, d_h2, d_el2, d_er2, bias2,
               er_s, gs, pnb_s, nbr_s, mask_s, cnt_s, el_s, inv_s);

    int lane = tid & 31, w = tid >> 5;
    int ia = lane, ib = lane + 32;
    float vg0 = gs[w * 64 + ia], vg1 = gs[w * 64 + ib];
    float vl0 = lh_s[w * 64 + ia], vl1 = lh_s[w * 64 + ib];
    float s1 = vg0 + vg1, s2 = vg0 * vg0 + vg1 * vg1;
    float s3 = vl0 + vl1, s4 = vl0 * vl0 + vl1 * vl1;
#pragma unroll
    for (int o = 16; o; o >>= 1) {
        s1 += __shfl_xor_sync(~0u, s1, o);
        s2 += __shfl_xor_sync(~0u, s2, o);
        s3 += __shfl_xor_sync(~0u, s3, o);
        s4 += __shfl_xor_sync(~0u, s4, o);
    }
    const float invH = 1.0f / 64.0f;
    float mug = s1 * invH, varg = s2 * invH - mug * mug;
    float mul_ = s3 * invH, varl = s4 * invH - mul_ * mul_;
    float rg = rsqrtf(varg + 1e-5f), rl = rsqrtf(varl + 1e-5f);
    float h0 = (vg0 - mug) * rg * gg[ia] + bg[ia] + (vl0 - mul_) * rl * gl[ia] + bl[ia];
    float h1v = (vg1 - mug) * rg * gg[ib] + bg[ib] + (vl1 - mul_) * rl * gl[ib] + bl[ib];
    __syncwarp();
    lh_s[w * 64 + ia] = h0;
    lh_s[w * 64 + ib] = h1v;
    __syncwarp();
    if (lane < NPRED) {
        float o = bd[lane];
#pragma unroll
        for (int k = 0; k < 64; k++) o += lh_s[w * 64 + k] * Wds[k * NPRED + lane];
        out[(size_t)(base + m0 + w) * NPRED + lane] = o;
    }
}

extern "C" void kernel_launch(void* const* d_in, const int* in_sizes, int n_in,
                              void* d_out, int out_size) {
    const float* x    = (const float*)d_in[0];
    const int*   ei   = (const int*)d_in[1];
    const float* Wfc  = (const float*)d_in[2];
    const float* bfc  = (const float*)d_in[3];
    const float* W1   = (const float*)d_in[4];
    const float* al1  = (const float*)d_in[5];
    const float* ar1  = (const float*)d_in[6];
    const float* bias1= (const float*)d_in[7];
    const float* W2   = (const float*)d_in[8];
    const float* al2  = (const float*)d_in[9];
    const float* ar2  = (const float*)d_in[10];
    const float* bias2= (const float*)d_in[11];
    const float* Wih  = (const float*)d_in[12];
    const float* Whh  = (const float*)d_in[13];
    const float* bih  = (const float*)d_in[14];
    const float* bhh  = (const float*)d_in[15];
    const float* gl   = (const float*)d_in[16];
    const float* bl   = (const float*)d_in[17];
    const float* gg   = (const float*)d_in[18];
    const float* bg   = (const float*)d_in[19];
    const float* Wd   = (const float*)d_in[20];
    const float* bd   = (const float*)d_in[21];
    float* out = (float*)d_out;

    int E = in_sizes[1] / 2;
    int maskBlocks = (E + 255) / 256;

    k_pre<<<136 + maskBlocks, 256>>>(x, Wfc, bfc, W1, al1, ar1, Wih, bih, bhh, Whh, ei, E);
    k_main<<<512, 256>>>(x, bias1, W2, al2, ar2);
    k_gat1<<<256, 256>>>(bias2, gl, bl, gg, bg, Wd, bd, out);
}